// round 14
// baseline (speedup 1.0000x reference)
#include <cuda_runtime.h>
#include <cuda_fp16.h>
#include <cstdint>

typedef unsigned long long ull;

// Problem constants
constexpr int NN = 100000;
constexpr int EE = 1250000;
constexpr int KTOT = 576;                 // 64 (root) + 8*64
constexpr int NK = NN * 8;                // (rel, dst) keys
constexpr int NBLK2 = (NK + 1023) / 1024; // 782 scan blocks
constexpr int NCH = 9;                    // 1 root chunk + 8 relation chunks
constexpr int AS = 72;                    // fp16 A/B smem row stride (144 B)
constexpr int EGRID = (EE + 255) / 256;   // 4883
constexpr int PG1 = (64 * KTOT) / 256;    // 144 blocks for W1 prep
constexpr int PG2 = (32 * KTOT) / 256;    // 72 blocks for W2 prep
constexpr int XG = (NN * 64) / (256 * 8); // 3125 blocks for x->fp16 convert

// ---------------- scratch ---------------------------------------------------
__device__ int g_cnt[NK];                 // zero at load; re-zeroed by k_scan
__device__ int g_rowptr[NK + 1];          // +1 sentinel (= EE)
__device__ int g_cursor[NK];
__device__ int g_epack[EE];               // src | (dst&15)<<20, sorted by (rel, dst)
__device__ unsigned int g_scanflag[NBLK2];
__device__ __half g_x16[(size_t)NN * 64]; // fp16 input features
__device__ __half g_H[(size_t)NN * 64];   // fp16 hidden layer
__device__ __half g_Agg[(size_t)NN * 512];// fp16 per-relation mean aggregates
__device__ __half g_Wt1h[64 * KTOT];
__device__ __half g_Wt1l[64 * KTOT];
__device__ __half g_Wt2h[32 * KTOT];
__device__ __half g_Wt2l[32 * KTOT];

// ---------------- helpers ---------------------------------------------------
__device__ __forceinline__ uint32_t smem_u32(const void* p) {
    uint32_t a;
    asm("{ .reg .u64 t; cvta.to.shared.u64 t, %1; cvt.u32.u64 %0, t; }" : "=r"(a) : "l"(p));
    return a;
}
__device__ __forceinline__ void sts128(uint32_t a, uint32_t x, uint32_t y, uint32_t z, uint32_t w) {
    asm volatile("st.shared.v4.b32 [%0], {%1,%2,%3,%4};" :: "r"(a), "r"(x), "r"(y), "r"(z), "r"(w) : "memory");
}
__device__ __forceinline__ void sts16(uint32_t a, unsigned short v) {
    asm volatile("st.shared.u16 [%0], %1;" :: "r"(a), "h"(v) : "memory");
}
__device__ __forceinline__ uint32_t lds32(uint32_t a) {
    uint32_t v;
    asm volatile("ld.shared.b32 %0, [%1];" : "=r"(v) : "r"(a));
    return v;
}
__device__ __forceinline__ uint32_t cvt2h(float lo, float hi) {
    uint32_t r;
    asm("cvt.rn.satfinite.f16x2.f32 %0, %1, %2;" : "=r"(r) : "f"(hi), "f"(lo));
    return r;
}
__device__ __forceinline__ void ldmx4(uint32_t* r, uint32_t a) {
    asm volatile("ldmatrix.sync.aligned.m8n8.x4.shared.b16 {%0,%1,%2,%3}, [%4];"
                 : "=r"(r[0]), "=r"(r[1]), "=r"(r[2]), "=r"(r[3]) : "r"(a));
}
__device__ __forceinline__ void ldmx4t(uint32_t* r, uint32_t a) {
    asm volatile("ldmatrix.sync.aligned.m8n8.x4.trans.shared.b16 {%0,%1,%2,%3}, [%4];"
                 : "=r"(r[0]), "=r"(r[1]), "=r"(r[2]), "=r"(r[3]) : "r"(a));
}
__device__ __forceinline__ void mma16816(float* c, const uint32_t* a, uint32_t b0, uint32_t b1) {
    asm volatile("mma.sync.aligned.m16n8k16.row.col.f32.f16.f16.f32 "
                 "{%0,%1,%2,%3}, {%4,%5,%6,%7}, {%8,%9}, {%0,%1,%2,%3};"
                 : "+f"(c[0]), "+f"(c[1]), "+f"(c[2]), "+f"(c[3])
                 : "r"(a[0]), "r"(a[1]), "r"(a[2]), "r"(a[3]), "r"(b0), "r"(b1));
}

// ---------------- CSR build over keys (rel*NN + dst) -------------------------
__global__ void k_count(const int* __restrict__ dst, const int* __restrict__ et) {
    int e = blockIdx.x * blockDim.x + threadIdx.x;
    if (e < NBLK2) g_scanflag[e] = 0;
    if (e < EE) atomicAdd(&g_cnt[et[e] * NN + dst[e]], 1);
}

__global__ void k_scan() {
    int t = threadIdx.x, b = blockIdx.x, i = b * 1024 + t;
    int lane = t & 31, wid = t >> 5;
    int orig = 0;
    if (i < NK) {
        orig = g_cnt[i];
        g_cnt[i] = 0;
    }
    int v = orig;
#pragma unroll
    for (int o = 1; o < 32; o <<= 1) {
        int nv = __shfl_up_sync(0xffffffffu, v, o);
        if (lane >= o) v += nv;
    }
    __shared__ int ws[32];
    __shared__ int s_prefix;
    if (lane == 31) ws[wid] = v;
    __syncthreads();
    if (wid == 0) {
        int wv = ws[lane];
#pragma unroll
        for (int o = 1; o < 32; o <<= 1) {
            int nv = __shfl_up_sync(0xffffffffu, wv, o);
            if (lane >= o) wv += nv;
        }
        ws[lane] = wv;
    }
    __syncthreads();
    int wpre = wid ? ws[wid - 1] : 0;
    int incl = wpre + v;
    if (t == 0) {
        int total = ws[31];
        if (b == 0) {
            atomicExch(&g_scanflag[0], ((unsigned)total << 2) | 2u);
            s_prefix = 0;
        } else {
            atomicExch(&g_scanflag[b], ((unsigned)total << 2) | 1u);
            int prefix = 0;
            for (int pb = b - 1;;) {
                unsigned wv;
                do { wv = atomicAdd(&g_scanflag[pb], 0u); } while ((wv & 3u) == 0u);
                prefix += (int)(wv >> 2);
                if ((wv & 3u) == 2u) break;
                pb--;
            }
            atomicExch(&g_scanflag[b], ((unsigned)(prefix + total) << 2) | 2u);
            s_prefix = prefix;
        }
    }
    __syncthreads();
    int prefix = s_prefix;
    if (i < NK) {
        int rv = prefix + incl - orig;
        g_rowptr[i] = rv;
        g_cursor[i] = rv;
    }
    if (i == 0) g_rowptr[NK] = EE;
}

// ------- merged: edge build + W transpose/split + x -> fp16 convert ----------
__device__ __forceinline__ void prep_one(const float* __restrict__ root,
                                         const float* __restrict__ W,
                                         __half* __restrict__ oh,
                                         __half* __restrict__ ol,
                                         int dout, int i) {
    int n = i / KTOT, k = i % KTOT;
    float v = (k < 64) ? root[k * dout + n] : W[(size_t)(k - 64) * dout + n];
    __half h = __float2half_rn(v);
    float lo = v - __half2float(h);
    oh[i] = h;
    ol[i] = __float2half_rn(lo);
}
__global__ void k_build_prep(const int* __restrict__ src, const int* __restrict__ dst,
                             const int* __restrict__ et, const float* __restrict__ x,
                             const float* __restrict__ root1, const float* __restrict__ W1,
                             const float* __restrict__ root2, const float* __restrict__ W2) {
    int b = blockIdx.x;
    if (b < EGRID) {
        int e = b * 256 + threadIdx.x;
        if (e < EE) {
            int d = dst[e];
            int p = atomicAdd(&g_cursor[et[e] * NN + d], 1);
            g_epack[p] = src[e] | ((d & 15) << 20);
        }
    } else if (b < EGRID + XG) {
        size_t i = ((size_t)(b - EGRID) * 256 + threadIdx.x) * 8;
        const float4* xp = reinterpret_cast<const float4*>(x + i);
        float4 v0 = xp[0], v1 = xp[1];
        uint4 o;
        o.x = cvt2h(v0.x, v0.y);
        o.y = cvt2h(v0.z, v0.w);
        o.z = cvt2h(v1.x, v1.y);
        o.w = cvt2h(v1.z, v1.w);
        *reinterpret_cast<uint4*>(g_x16 + i) = o;
    } else if (b < EGRID + XG + PG1) {
        prep_one(root1, W1, g_Wt1h, g_Wt1l, 64, (b - EGRID - XG) * 256 + threadIdx.x);
    } else {
        prep_one(root2, W2, g_Wt2h, g_Wt2l, 32, (b - EGRID - XG - PG1) * 256 + threadIdx.x);
    }
}

// ---------------- aggregation via tensor-core segment-sum --------------------
// CSR sorted by (rel, dst): warp's 16 nodes have contiguous edges per rel.
// Per 16-edge batch: one-hot selector S[16 nodes][16 edges] (fp16, smem) and
// gathered E[16 edges][64 cols] tile; D += S x E via 8 HMMA (fp32 acc).
// Per-warp smem: E tile 16x144B (2304) + selector 16x48B (768) = 3072 B.
__global__ __launch_bounds__(256, 3) void k_agg(const __half* __restrict__ F,
                                                __half* __restrict__ Agg) {
    __shared__ __align__(16) char smem[8 * 3072];
    int tid = threadIdx.x, w = tid >> 5, l = tid & 31;
    uint32_t ebase = smem_u32(smem) + w * 3072;
    uint32_t selbase = ebase + 2304;
    int nb = blockIdx.x * 128 + w * 16;

    // zero selector (cleared after each batch thereafter)
    sts128(selbase + l * 16, 0u, 0u, 0u, 0u);
    if (l < 16) sts128(selbase + 512 + l * 16, 0u, 0u, 0u, 0u);
    __syncwarp();

    // frag addresses
    int lrow = (l & 7) + ((l >> 3) & 1) * 8;
    uint32_t saddr = selbase + (uint32_t)(lrow * 48) + ((l >> 4) & 1) * 16;
    uint32_t baddr = ebase + (uint32_t)(lrow * 144) + ((l >> 4) & 1) * 16;

    for (int r = 0; r < 8; r++) {
        // metadata: rowptr[r*NN + nb + l] for l<=16
        int rp = 0;
        if (l < 17) rp = __ldg(g_rowptr + r * NN + min(nb + l, NN));
        int st = __shfl_sync(0xffffffffu, rp, 0);
        int en = __shfl_sync(0xffffffffu, rp, 16);
        int nxt = __shfl_sync(0xffffffffu, rp, (l + 1) & 31);
        int cnt = nxt - rp;                       // valid for l<16
        float invv = 1.0f / (float)max(cnt, 1);

        float acc[8][4];
#pragma unroll
        for (int t = 0; t < 8; t++)
#pragma unroll
            for (int q = 0; q < 4; q++) acc[t][q] = 0.f;

        for (int base = st; base < en; base += 16) {
            int j = base + (l & 15);
            int rec = 0;
            int slot = -1;
            bool act = (l < 16) && (j < en);
            if (act) {
                rec = __ldg(g_epack + j);
                slot = (rec >> 20) & 15;
                sts16(selbase + slot * 48 + (l & 15) * 2, (unsigned short)0x3C00);
            }
            // E tile: 4 passes, 4 rows each; lane covers 16 B of row
#pragma unroll
            for (int ps = 0; ps < 4; ps++) {
                int e = ps * 4 + (l >> 3);
                int rsrc = __shfl_sync(0xffffffffu, rec, e);
                int srci = rsrc & 0xFFFFF;
                uint4 v = *(reinterpret_cast<const uint4*>(F + (size_t)srci * 64) + (l & 7));
                sts128(ebase + (uint32_t)(e * 144) + (l & 7) * 16, v.x, v.y, v.z, v.w);
            }
            __syncwarp();
            uint32_t sa[4];
            ldmx4(sa, saddr);
#pragma unroll
            for (int q = 0; q < 4; q++) {
                uint32_t bf[4];
                ldmx4t(bf, baddr + q * 32);
                mma16816(acc[2 * q], sa, bf[0], bf[1]);
                mma16816(acc[2 * q + 1], sa, bf[2], bf[3]);
            }
            __syncwarp();
            if (act) sts16(selbase + slot * 48 + (l & 15) * 2, (unsigned short)0);
            __syncwarp();
        }

        // epilogue: normalize + cvt + store
        int row0 = l >> 2;
        float inv0 = __shfl_sync(0xffffffffu, invv, row0);
        float inv1 = __shfl_sync(0xffffffffu, invv, row0 + 8);
        int mg0 = nb + row0, mg1 = nb + row0 + 8;
        int coff = r * 64 + (l & 3) * 2;
#pragma unroll
        for (int t = 0; t < 8; t++) {
            if (mg0 < NN)
                *reinterpret_cast<uint32_t*>(Agg + (size_t)mg0 * 512 + coff + t * 8) =
                    cvt2h(acc[t][0] * inv0, acc[t][1] * inv0);
            if (mg1 < NN)
                *reinterpret_cast<uint32_t*>(Agg + (size_t)mg1 * 512 + coff + t * 8) =
                    cvt2h(acc[t][2] * inv1, acc[t][3] * inv1);
        }
    }
}

// ---------------- lean tiled GEMM: out = act(bias + [F|Agg] @ Wt^T) ----------
template <int DOUT, bool RELU, bool OUT16>
__global__ __launch_bounds__(256, 3) void k_gemm(
    const __half* __restrict__ F, const __half* __restrict__ Agg,
    const __half* __restrict__ Wth, const __half* __restrict__ Wtl,
    const float* __restrict__ bias, void* __restrict__ outv) {
    constexpr int NT = DOUT / 8;
    constexpr int BP = 256 / DOUT;
    constexpr int BV = (64 * 2 / BP) / 16;

    extern __shared__ __align__(16) char dyn[];
    uint32_t sA = smem_u32(dyn);
    uint32_t sBh = sA + 128 * AS * 2;
    uint32_t sBl = sBh + DOUT * AS * 2;

    int tid = threadIdx.x;
    int w = tid >> 5, l = tid & 31;
    int m0 = blockIdx.x * 128;

    int jl = l & 7, ns = l >> 3;

    int bn = tid % DOUT, bpart = tid / DOUT;
    uint4 bh4[BV], bl4[BV];
    auto loadB = [&](int c) {
        size_t off = (size_t)bn * KTOT + c * 64;
        const uint4* bh = reinterpret_cast<const uint4*>(Wth + off) + bpart * BV;
        const uint4* bl = reinterpret_cast<const uint4*>(Wtl + off) + bpart * BV;
#pragma unroll
        for (int v = 0; v < BV; v++) { bh4[v] = bh[v]; bl4[v] = bl[v]; }
    };
    auto storeB = [&]() {
        uint32_t bbase = (uint32_t)(bn * (AS * 2) + bpart * (BV * 16));
#pragma unroll
        for (int v = 0; v < BV; v++) {
            sts128(sBh + bbase + v * 16, bh4[v].x, bh4[v].y, bh4[v].z, bh4[v].w);
            sts128(sBl + bbase + v * 16, bl4[v].x, bl4[v].y, bl4[v].z, bl4[v].w);
        }
    };

    uint4 av[4];
    auto loadA = [&](int c) {
#pragma unroll
        for (int p = 0; p < 4; p++) {
            int mg = m0 + w * 16 + p * 4 + ns;
            if (mg < NN) {
                const __half* base = (c == 0) ? (F + (size_t)mg * 64)
                                              : (Agg + (size_t)mg * 512 + (c - 1) * 64);
                av[p] = *(reinterpret_cast<const uint4*>(base) + jl);
            } else {
                av[p] = make_uint4(0u, 0u, 0u, 0u);
            }
        }
    };
    auto storeA = [&]() {
#pragma unroll
        for (int p = 0; p < 4; p++) {
            int nrow = w * 16 + p * 4 + ns;
            sts128(sA + (uint32_t)(nrow * (AS * 2)) + jl * 16,
                   av[p].x, av[p].y, av[p].z, av[p].w);
        }
    };

    float acc[NT][4];
#pragma unroll
    for (int t = 0; t < NT; t++)
#pragma unroll
        for (int q = 0; q < 4; q++) acc[t][q] = 0.f;

    int lrow = w * 16 + (l & 7) + ((l >> 3) & 1) * 8;
    uint32_t aoff = (uint32_t)(lrow * (AS * 2)) + ((l >> 4) & 1) * 16;
    int bfn = l >> 2;
    int bfk = (l & 3) * 4;

    loadB(0);
    loadA(0);
    for (int c = 0; c < NCH; c++) {
        storeB();
        storeA();
        __syncthreads();
        if (c + 1 < NCH) { loadB(c + 1); loadA(c + 1); }
#pragma unroll
        for (int ks = 0; ks < 4; ks++) {
            uint32_t fa[4];
            ldmx4(fa, sA + aoff + ks * 32);
#pragma unroll
            for (int t = 0; t < NT; t++) {
                uint32_t ba = (uint32_t)((t * 8 + bfn) * (AS * 2)) + ks * 32 + bfk;
                uint32_t bh0 = lds32(sBh + ba), bh1 = lds32(sBh + ba + 16);
                uint32_t bl0 = lds32(sBl + ba), bl1 = lds32(sBl + ba + 16);
                mma16816(acc[t], fa, bh0, bh1);
                mma16816(acc[t], fa, bl0, bl1);
            }
        }
        __syncthreads();
    }

    int r0 = m0 + w * 16 + (l >> 2);
    int cb = (l & 3) * 2;
#pragma unroll
    for (int t = 0; t < NT; t++) {
        int n = t * 8 + cb;
        float b0 = __ldg(bias + n), b1 = __ldg(bias + n + 1);
        float v0 = acc[t][0] + b0, v1 = acc[t][1] + b1;
        float v2 = acc[t][2] + b0, v3 = acc[t][3] + b1;
        if (RELU) {
            v0 = fmaxf(v0, 0.f); v1 = fmaxf(v1, 0.f);
            v2 = fmaxf(v2, 0.f); v3 = fmaxf(v3, 0.f);
        }
        if (OUT16) {
            __half* o16 = reinterpret_cast<__half*>(outv);
            if (r0 < NN)
                *reinterpret_cast<uint32_t*>(o16 + (size_t)r0 * DOUT + n) = cvt2h(v0, v1);
            if (r0 + 8 < NN)
                *reinterpret_cast<uint32_t*>(o16 + (size_t)(r0 + 8) * DOUT + n) = cvt2h(v2, v3);
        } else {
            float* of = reinterpret_cast<float*>(outv);
            if (r0 < NN)
                *reinterpret_cast<float2*>(of + (size_t)r0 * DOUT + n) = make_float2(v0, v1);
            if (r0 + 8 < NN)
                *reinterpret_cast<float2*>(of + (size_t)(r0 + 8) * DOUT + n) = make_float2(v2, v3);
        }
    }
}

// ---------------- launch ----------------------------------------------------
extern "C" void kernel_launch(void* const* d_in, const int* in_sizes, int n_in,
                              void* d_out, int out_size) {
    const float* x     = (const float*)d_in[0];
    const float* W1    = (const float*)d_in[1];
    const float* root1 = (const float*)d_in[2];
    const float* b1    = (const float*)d_in[3];
    const float* W2    = (const float*)d_in[4];
    const float* root2 = (const float*)d_in[5];
    const float* b2    = (const float*)d_in[6];
    const int*   src   = (const int*)d_in[7];
    const int*   dst   = (const int*)d_in[8];
    const int*   et    = (const int*)d_in[9];

    __half *H, *x16, *Agg, *w1h, *w1l, *w2h, *w2l;
    cudaGetSymbolAddress((void**)&H, g_H);
    cudaGetSymbolAddress((void**)&x16, g_x16);
    cudaGetSymbolAddress((void**)&Agg, g_Agg);
    cudaGetSymbolAddress((void**)&w1h, g_Wt1h);
    cudaGetSymbolAddress((void**)&w1l, g_Wt1l);
    cudaGetSymbolAddress((void**)&w2h, g_Wt2h);
    cudaGetSymbolAddress((void**)&w2l, g_Wt2l);

    const int ggrid = (NN + 127) / 128;
    const int smA = 128 * AS * 2;
    const int smem64 = smA + 2 * 64 * AS * 2;   // 36864
    const int smem32 = smA + 2 * 32 * AS * 2;   // 27648

    static bool attr_done = false;
    if (!attr_done) {
        cudaFuncSetAttribute(k_gemm<64, true, true>,
                             cudaFuncAttributeMaxDynamicSharedMemorySize, smem64);
        cudaFuncSetAttribute(k_gemm<32, false, false>,
                             cudaFuncAttributeMaxDynamicSharedMemorySize, smem32);
        attr_done = true;
    }

    // CSR build over (rel, dst) keys (g_cnt pre-zeroed by previous call's k_scan)
    k_count<<<EGRID, 256>>>(dst, et);
    k_scan<<<NBLK2, 1024>>>();
    k_build_prep<<<EGRID + XG + PG1 + PG2, 256>>>(src, dst, et, x,
                                                  root1, W1, root2, W2);

    // Layer 1: tensor-core aggregate then GEMM (H written fp16)
    k_agg<<<ggrid, 256>>>(x16, Agg);
    k_gemm<64, true, true><<<ggrid, 256, smem64>>>(x16, Agg, w1h, w1l, b1, H);

    // Layer 2: aggregate H then GEMM -> fp32 output
    k_agg<<<ggrid, 256>>>(H, Agg);
    k_gemm<32, false, false><<<ggrid, 256, smem32>>>(H, Agg, w2h, w2l, b2, d_out);
}

// round 15
// speedup vs baseline: 1.3620x; 1.3620x over previous
#include <cuda_runtime.h>
#include <cuda_fp16.h>
#include <cstdint>

typedef unsigned long long ull;

// Problem constants
constexpr int NN = 100000;
constexpr int EE = 1250000;
constexpr int KTOT = 576;                 // 64 (root) + 8*64
constexpr int NK = NN * 8;                // (dst, rel) keys
constexpr int NBLK2 = (NK + 1023) / 1024; // 782 scan blocks
constexpr int NCH = 9;                    // 1 root chunk + 8 relation chunks
constexpr int AS = 72;                    // fp16 A/B smem row stride (144 B)
constexpr int EGRID = (EE + 255) / 256;   // 4883
constexpr int PG1 = (64 * KTOT) / 256;    // 144 blocks for W1 prep
constexpr int PG2 = (32 * KTOT) / 256;    // 72 blocks for W2 prep
constexpr int XG = (NN * 64) / (256 * 8); // 3125 blocks for x->fp16 convert

// ---------------- scratch ---------------------------------------------------
__device__ int g_cnt[NK];                 // zero at load; re-zeroed by k_scan
__device__ int g_rowptr[NK + 1];          // +1 sentinel (= EE)
__device__ int g_cursor[NK];
__device__ int g_epack[EE];               // src ids sorted by (dst, rel)
__device__ unsigned int g_scanflag[NBLK2];
__device__ __half g_x16[(size_t)NN * 64]; // fp16 input features
__device__ __half g_H[(size_t)NN * 64];   // fp16 hidden layer
__device__ __half g_Agg[(size_t)NN * 512];// fp16 per-relation mean aggregates
__device__ __half g_Wt1[64 * KTOT];       // fp16 transposed [root1|W1]
__device__ __half g_Wt2[32 * KTOT];       // fp16 transposed [root2|W2]

// ---------------- helpers ---------------------------------------------------
__device__ __forceinline__ uint32_t smem_u32(const void* p) {
    uint32_t a;
    asm("{ .reg .u64 t; cvta.to.shared.u64 t, %1; cvt.u32.u64 %0, t; }" : "=r"(a) : "l"(p));
    return a;
}
__device__ __forceinline__ void sts128(uint32_t a, uint32_t x, uint32_t y, uint32_t z, uint32_t w) {
    asm volatile("st.shared.v4.b32 [%0], {%1,%2,%3,%4};" :: "r"(a), "r"(x), "r"(y), "r"(z), "r"(w) : "memory");
}
__device__ __forceinline__ uint32_t lds32(uint32_t a) {
    uint32_t v;
    asm volatile("ld.shared.b32 %0, [%1];" : "=r"(v) : "r"(a));
    return v;
}
__device__ __forceinline__ uint32_t cvt2h(float lo, float hi) {
    uint32_t r;
    asm("cvt.rn.satfinite.f16x2.f32 %0, %1, %2;" : "=r"(r) : "f"(hi), "f"(lo));
    return r;
}
__device__ __forceinline__ void ldmx4(uint32_t* r, uint32_t a) {
    asm volatile("ldmatrix.sync.aligned.m8n8.x4.shared.b16 {%0,%1,%2,%3}, [%4];"
                 : "=r"(r[0]), "=r"(r[1]), "=r"(r[2]), "=r"(r[3]) : "r"(a));
}
__device__ __forceinline__ void mma16816(float* c, const uint32_t* a, uint32_t b0, uint32_t b1) {
    asm volatile("mma.sync.aligned.m16n8k16.row.col.f32.f16.f16.f32 "
                 "{%0,%1,%2,%3}, {%4,%5,%6,%7}, {%8,%9}, {%0,%1,%2,%3};"
                 : "+f"(c[0]), "+f"(c[1]), "+f"(c[2]), "+f"(c[3])
                 : "r"(a[0]), "r"(a[1]), "r"(a[2]), "r"(a[3]), "r"(b0), "r"(b1));
}

// ---------------- CSR build over keys (dst*8 + rel) --------------------------
__global__ void k_count(const int* __restrict__ dst, const int* __restrict__ et) {
    int e = blockIdx.x * blockDim.x + threadIdx.x;
    if (e < NBLK2) g_scanflag[e] = 0;
    if (e < EE) atomicAdd(&g_cnt[dst[e] * 8 + et[e]], 1);
}

__global__ void k_scan() {
    int t = threadIdx.x, b = blockIdx.x, i = b * 1024 + t;
    int lane = t & 31, wid = t >> 5;
    int orig = 0;
    if (i < NK) {
        orig = g_cnt[i];
        g_cnt[i] = 0;
    }
    int v = orig;
#pragma unroll
    for (int o = 1; o < 32; o <<= 1) {
        int nv = __shfl_up_sync(0xffffffffu, v, o);
        if (lane >= o) v += nv;
    }
    __shared__ int ws[32];
    __shared__ int s_prefix;
    if (lane == 31) ws[wid] = v;
    __syncthreads();
    if (wid == 0) {
        int wv = ws[lane];
#pragma unroll
        for (int o = 1; o < 32; o <<= 1) {
            int nv = __shfl_up_sync(0xffffffffu, wv, o);
            if (lane >= o) wv += nv;
        }
        ws[lane] = wv;
    }
    __syncthreads();
    int wpre = wid ? ws[wid - 1] : 0;
    int incl = wpre + v;
    if (t == 0) {
        int total = ws[31];
        if (b == 0) {
            atomicExch(&g_scanflag[0], ((unsigned)total << 2) | 2u);
            s_prefix = 0;
        } else {
            atomicExch(&g_scanflag[b], ((unsigned)total << 2) | 1u);
            int prefix = 0;
            for (int pb = b - 1;;) {
                unsigned wv;
                do { wv = atomicAdd(&g_scanflag[pb], 0u); } while ((wv & 3u) == 0u);
                prefix += (int)(wv >> 2);
                if ((wv & 3u) == 2u) break;
                pb--;
            }
            atomicExch(&g_scanflag[b], ((unsigned)(prefix + total) << 2) | 2u);
            s_prefix = prefix;
        }
    }
    __syncthreads();
    int prefix = s_prefix;
    if (i < NK) {
        int rv = prefix + incl - orig;
        g_rowptr[i] = rv;
        g_cursor[i] = rv;
    }
    if (i == 0) g_rowptr[NK] = EE;
}

// ------- merged: edge build + W transpose (fp16) + x -> fp16 convert ---------
__device__ __forceinline__ void prep_one(const float* __restrict__ root,
                                         const float* __restrict__ W,
                                         __half* __restrict__ oh,
                                         int dout, int i) {
    int n = i / KTOT, k = i % KTOT;
    float v = (k < 64) ? root[k * dout + n] : W[(size_t)(k - 64) * dout + n];
    oh[i] = __float2half_rn(v);
}
__global__ void k_build_prep(const int* __restrict__ src, const int* __restrict__ dst,
                             const int* __restrict__ et, const float* __restrict__ x,
                             const float* __restrict__ root1, const float* __restrict__ W1,
                             const float* __restrict__ root2, const float* __restrict__ W2) {
    int b = blockIdx.x;
    if (b < EGRID) {
        int e = b * 256 + threadIdx.x;
        if (e < EE) {
            int p = atomicAdd(&g_cursor[dst[e] * 8 + et[e]], 1);
            g_epack[p] = src[e];
        }
    } else if (b < EGRID + XG) {
        size_t i = ((size_t)(b - EGRID) * 256 + threadIdx.x) * 8;
        const float4* xp = reinterpret_cast<const float4*>(x + i);
        float4 v0 = xp[0], v1 = xp[1];
        uint4 o;
        o.x = cvt2h(v0.x, v0.y);
        o.y = cvt2h(v0.z, v0.w);
        o.z = cvt2h(v1.x, v1.y);
        o.w = cvt2h(v1.z, v1.w);
        *reinterpret_cast<uint4*>(g_x16 + i) = o;
    } else if (b < EGRID + XG + PG1) {
        prep_one(root1, W1, g_Wt1, 64, (b - EGRID - XG) * 256 + threadIdx.x);
    } else {
        prep_one(root2, W2, g_Wt2, 32, (b - EGRID - XG - PG1) * 256 + threadIdx.x);
    }
}

// ---------------- aggregation: fp16 gather -> fp16 Agg[N][512] ---------------
// (R13-proven scalar form.) Warp = 16 nodes (4 streams x 4 sub-nodes); lane
// owns 16 B of the 128 B row. fp32 register accumulation.
__global__ __launch_bounds__(256, 3) void k_agg(const __half* __restrict__ F,
                                                __half* __restrict__ Agg) {
    int tid = threadIdx.x, w = tid >> 5, l = tid & 31;
    int jl = l & 7, ns = l >> 3;
    int m0 = blockIdx.x * 128;

    for (int r = 0; r < 8; r++) {
        int st[4], cn[4];
#pragma unroll
        for (int p = 0; p < 4; p++) {
            int mg = m0 + w * 16 + p * 4 + ns;
            if (mg < NN) {
                int key = mg * 8 + r;
                int s0 = __ldg(g_rowptr + key);
                st[p] = s0;
                cn[p] = __ldg(g_rowptr + key + 1) - s0;
            } else {
                st[p] = 0;
                cn[p] = 0;
            }
        }
        int mx = max(max(cn[0], cn[1]), max(cn[2], cn[3]));
        float4 a0[4], a1[4];
#pragma unroll
        for (int p = 0; p < 4; p++) {
            a0[p] = make_float4(0.f, 0.f, 0.f, 0.f);
            a1[p] = make_float4(0.f, 0.f, 0.f, 0.f);
        }
        int rec[4];
#pragma unroll
        for (int p = 0; p < 4; p++)
            rec[p] = (cn[p] > 0) ? __ldg(g_epack + st[p]) : -1;
        for (int j = 0; j < mx; j++) {
            uint4 v[4];
#pragma unroll
            for (int p = 0; p < 4; p++) {
                if (rec[p] >= 0)
                    v[p] = *(reinterpret_cast<const uint4*>(F + (size_t)rec[p] * 64) + jl);
            }
#pragma unroll
            for (int p = 0; p < 4; p++) {
                bool more = (j + 1 < cn[p]);
                int nr = more ? __ldg(g_epack + st[p] + j + 1) : -1;
                if (rec[p] >= 0) {
                    float2 f0 = __half22float2(*reinterpret_cast<__half2*>(&v[p].x));
                    float2 f1 = __half22float2(*reinterpret_cast<__half2*>(&v[p].y));
                    float2 f2 = __half22float2(*reinterpret_cast<__half2*>(&v[p].z));
                    float2 f3 = __half22float2(*reinterpret_cast<__half2*>(&v[p].w));
                    a0[p].x += f0.x; a0[p].y += f0.y;
                    a0[p].z += f1.x; a0[p].w += f1.y;
                    a1[p].x += f2.x; a1[p].y += f2.y;
                    a1[p].z += f3.x; a1[p].w += f3.y;
                }
                rec[p] = nr;
            }
        }
#pragma unroll
        for (int p = 0; p < 4; p++) {
            int mg = m0 + w * 16 + p * 4 + ns;
            if (mg < NN) {
                float inv = 1.0f / (float)max(cn[p], 1);
                uint4 o;
                o.x = cvt2h(a0[p].x * inv, a0[p].y * inv);
                o.y = cvt2h(a0[p].z * inv, a0[p].w * inv);
                o.z = cvt2h(a1[p].x * inv, a1[p].y * inv);
                o.w = cvt2h(a1[p].z * inv, a1[p].w * inv);
                *(reinterpret_cast<uint4*>(Agg + (size_t)mg * 512 + r * 64) + jl) = o;
            }
        }
    }
}

// -------- lean tiled GEMM (single fp16 pass): out = act(bias + [F|Agg]@Wt^T) -
template <int DOUT, bool RELU, bool OUT16>
__global__ __launch_bounds__(256, 3) void k_gemm(
    const __half* __restrict__ F, const __half* __restrict__ Agg,
    const __half* __restrict__ Wt,
    const float* __restrict__ bias, void* __restrict__ outv) {
    constexpr int NT = DOUT / 8;
    constexpr int BP = 256 / DOUT;          // threads per B row
    constexpr int BV = (64 * 2 / BP) / 16;  // uint4 per thread

    extern __shared__ __align__(16) char dyn[];
    uint32_t sA = smem_u32(dyn);
    uint32_t sB = sA + 128 * AS * 2;

    int tid = threadIdx.x;
    int w = tid >> 5, l = tid & 31;
    int m0 = blockIdx.x * 128;

    int jl = l & 7, ns = l >> 3;

    int bn = tid % DOUT, bpart = tid / DOUT;
    uint4 b4[BV];
    auto loadB = [&](int c) {
        size_t off = (size_t)bn * KTOT + c * 64;
        const uint4* bp = reinterpret_cast<const uint4*>(Wt + off) + bpart * BV;
#pragma unroll
        for (int v = 0; v < BV; v++) b4[v] = bp[v];
    };
    auto storeB = [&]() {
        uint32_t bbase = (uint32_t)(bn * (AS * 2) + bpart * (BV * 16));
#pragma unroll
        for (int v = 0; v < BV; v++)
            sts128(sB + bbase + v * 16, b4[v].x, b4[v].y, b4[v].z, b4[v].w);
    };

    uint4 av[4];
    auto loadA = [&](int c) {
#pragma unroll
        for (int p = 0; p < 4; p++) {
            int mg = m0 + w * 16 + p * 4 + ns;
            if (mg < NN) {
                const __half* base = (c == 0) ? (F + (size_t)mg * 64)
                                              : (Agg + (size_t)mg * 512 + (c - 1) * 64);
                av[p] = *(reinterpret_cast<const uint4*>(base) + jl);
            } else {
                av[p] = make_uint4(0u, 0u, 0u, 0u);
            }
        }
    };
    auto storeA = [&]() {
#pragma unroll
        for (int p = 0; p < 4; p++) {
            int nrow = w * 16 + p * 4 + ns;
            sts128(sA + (uint32_t)(nrow * (AS * 2)) + jl * 16,
                   av[p].x, av[p].y, av[p].z, av[p].w);
        }
    };

    float acc[NT][4];
#pragma unroll
    for (int t = 0; t < NT; t++)
#pragma unroll
        for (int q = 0; q < 4; q++) acc[t][q] = 0.f;

    int lrow = w * 16 + (l & 7) + ((l >> 3) & 1) * 8;
    uint32_t aoff = (uint32_t)(lrow * (AS * 2)) + ((l >> 4) & 1) * 16;
    int bfn = l >> 2;
    int bfk = (l & 3) * 4;

    loadB(0);
    loadA(0);
    for (int c = 0; c < NCH; c++) {
        storeB();
        storeA();
        __syncthreads();
        if (c + 1 < NCH) { loadB(c + 1); loadA(c + 1); }
#pragma unroll
        for (int ks = 0; ks < 4; ks++) {
            uint32_t fa[4];
            ldmx4(fa, sA + aoff + ks * 32);
#pragma unroll
            for (int t = 0; t < NT; t++) {
                uint32_t ba = (uint32_t)((t * 8 + bfn) * (AS * 2)) + ks * 32 + bfk;
                uint32_t b0 = lds32(sB + ba), b1 = lds32(sB + ba + 16);
                mma16816(acc[t], fa, b0, b1);
            }
        }
        __syncthreads();
    }

    int r0 = m0 + w * 16 + (l >> 2);
    int cb = (l & 3) * 2;
#pragma unroll
    for (int t = 0; t < NT; t++) {
        int n = t * 8 + cb;
        float b0 = __ldg(bias + n), b1 = __ldg(bias + n + 1);
        float v0 = acc[t][0] + b0, v1 = acc[t][1] + b1;
        float v2 = acc[t][2] + b0, v3 = acc[t][3] + b1;
        if (RELU) {
            v0 = fmaxf(v0, 0.f); v1 = fmaxf(v1, 0.f);
            v2 = fmaxf(v2, 0.f); v3 = fmaxf(v3, 0.f);
        }
        if (OUT16) {
            __half* o16 = reinterpret_cast<__half*>(outv);
            if (r0 < NN)
                *reinterpret_cast<uint32_t*>(o16 + (size_t)r0 * DOUT + n) = cvt2h(v0, v1);
            if (r0 + 8 < NN)
                *reinterpret_cast<uint32_t*>(o16 + (size_t)(r0 + 8) * DOUT + n) = cvt2h(v2, v3);
        } else {
            float* of = reinterpret_cast<float*>(outv);
            if (r0 < NN)
                *reinterpret_cast<float2*>(of + (size_t)r0 * DOUT + n) = make_float2(v0, v1);
            if (r0 + 8 < NN)
                *reinterpret_cast<float2*>(of + (size_t)(r0 + 8) * DOUT + n) = make_float2(v2, v3);
        }
    }
}

// ---------------- launch ----------------------------------------------------
extern "C" void kernel_launch(void* const* d_in, const int* in_sizes, int n_in,
                              void* d_out, int out_size) {
    const float* x     = (const float*)d_in[0];
    const float* W1    = (const float*)d_in[1];
    const float* root1 = (const float*)d_in[2];
    const float* b1    = (const float*)d_in[3];
    const float* W2    = (const float*)d_in[4];
    const float* root2 = (const float*)d_in[5];
    const float* b2    = (const float*)d_in[6];
    const int*   src   = (const int*)d_in[7];
    const int*   dst   = (const int*)d_in[8];
    const int*   et    = (const int*)d_in[9];

    __half *H, *x16, *Agg, *w1, *w2;
    cudaGetSymbolAddress((void**)&H, g_H);
    cudaGetSymbolAddress((void**)&x16, g_x16);
    cudaGetSymbolAddress((void**)&Agg, g_Agg);
    cudaGetSymbolAddress((void**)&w1, g_Wt1);
    cudaGetSymbolAddress((void**)&w2, g_Wt2);

    const int ggrid = (NN + 127) / 128;
    const int smA = 128 * AS * 2;
    const int smem64 = smA + 64 * AS * 2;   // 27648
    const int smem32 = smA + 32 * AS * 2;   // 23040

    static bool attr_done = false;
    if (!attr_done) {
        cudaFuncSetAttribute(k_gemm<64, true, true>,
                             cudaFuncAttributeMaxDynamicSharedMemorySize, smem64);
        cudaFuncSetAttribute(k_gemm<32, false, false>,
                             cudaFuncAttributeMaxDynamicSharedMemorySize, smem32);
        attr_done = true;
    }

    // CSR build over (dst, rel) keys (g_cnt pre-zeroed by previous call's k_scan)
    k_count<<<EGRID, 256>>>(dst, et);
    k_scan<<<NBLK2, 1024>>>();
    k_build_prep<<<EGRID + XG + PG1 + PG2, 256>>>(src, dst, et, x,
                                                  root1, W1, root2, W2);

    // Layer 1: aggregate then GEMM (H written fp16)
    k_agg<<<ggrid, 256>>>(x16, Agg);
    k_gemm<64, true, true><<<ggrid, 256, smem64>>>(x16, Agg, w1, b1, H);

    // Layer 2: aggregate H then GEMM -> fp32 output
    k_agg<<<ggrid, 256>>>(H, Agg);
    k_gemm<32, false, false><<<ggrid, 256, smem32>>>(H, Agg, w2, b2, d_out);
}